// round 3
// baseline (speedup 1.0000x reference)
#include <cuda_runtime.h>
#include <math.h>

// Problem shape (fixed by the reference)
#define NSAMP 2048
#define OBS   48
// Layers: (out, in)
// L0: 512 x 48   L1: 256 x 512   L2: 128 x 256   L3: 12 x 128

#define THREADS 256
#define SAMPLES_PER_CTA 2

__device__ __forceinline__ float elu(float s) {
    return (s > 0.0f) ? s : (__expf(s) - 1.0f);
}

// Two rows per group per iteration: 8 independent weight loads in flight
// before any dependent FMA/reduce. Biases prefetched before the dot loop.
// Requires OUT % (2 * THREADS/G) == 0.
template <int OUT, int IN, int G, bool ACT>
__device__ __forceinline__ void layer2(const float* __restrict__ W,
                                       const float* __restrict__ b,
                                       const float* __restrict__ x,
                                       float* __restrict__ y) {
    constexpr int NV = IN / 4;          // float4 per row
    constexpr int NG = THREADS / G;     // groups per block
    const int gid = threadIdx.x / G;
    const int gl  = threadIdx.x % G;
    const float4* __restrict__ xv = reinterpret_cast<const float4*>(x);

    #pragma unroll
    for (int row = gid; row < OUT; row += 2 * NG) {
        const int row1 = row + NG;
        // Prefetch biases so they overlap the weight stream (lane 0 only uses them).
        float bias0 = __ldcs(b + row);
        float bias1 = __ldcs(b + row1);
        const float4* __restrict__ Wr0 =
            reinterpret_cast<const float4*>(W + (size_t)row  * IN);
        const float4* __restrict__ Wr1 =
            reinterpret_cast<const float4*>(W + (size_t)row1 * IN);
        float s0 = 0.0f, s1 = 0.0f;
        #pragma unroll
        for (int j = gl; j < NV; j += G) {
            float4 w0 = __ldcs(Wr0 + j);
            float4 w1 = __ldcs(Wr1 + j);
            float4 v  = xv[j];
            s0 = fmaf(w0.x, v.x, s0);
            s0 = fmaf(w0.y, v.y, s0);
            s0 = fmaf(w0.z, v.z, s0);
            s0 = fmaf(w0.w, v.w, s0);
            s1 = fmaf(w1.x, v.x, s1);
            s1 = fmaf(w1.y, v.y, s1);
            s1 = fmaf(w1.z, v.z, s1);
            s1 = fmaf(w1.w, v.w, s1);
        }
        #pragma unroll
        for (int o = G / 2; o >= 1; o >>= 1) {
            s0 += __shfl_xor_sync(0xffffffffu, s0, o);
            s1 += __shfl_xor_sync(0xffffffffu, s1, o);
        }
        if (gl == 0) {
            s0 += bias0;
            s1 += bias1;
            if (ACT) { s0 = elu(s0); s1 = elu(s1); }
            y[row]  = s0;
            y[row1] = s1;
        }
    }
}

// Single-row variant for the tiny final layer.
template <int OUT, int IN, int G, bool ACT>
__device__ __forceinline__ void layer1(const float* __restrict__ W,
                                       const float* __restrict__ b,
                                       const float* __restrict__ x,
                                       float* __restrict__ y) {
    constexpr int NV = IN / 4;
    constexpr int NG = THREADS / G;
    const int gid = threadIdx.x / G;
    const int gl  = threadIdx.x % G;
    const float4* __restrict__ xv = reinterpret_cast<const float4*>(x);

    for (int row = gid; row < OUT; row += NG) {
        float bias = __ldcs(b + row);
        const float4* __restrict__ Wr =
            reinterpret_cast<const float4*>(W + (size_t)row * IN);
        float s = 0.0f;
        #pragma unroll
        for (int j = gl; j < NV; j += G) {
            float4 w = __ldcs(Wr + j);
            float4 v = xv[j];
            s = fmaf(w.x, v.x, s);
            s = fmaf(w.y, v.y, s);
            s = fmaf(w.z, v.z, s);
            s = fmaf(w.w, v.w, s);
        }
        #pragma unroll
        for (int o = G / 2; o >= 1; o >>= 1)
            s += __shfl_xor_sync(0xffffffffu, s, o);
        if (gl == 0) {
            s += bias;
            if (ACT) s = elu(s);
            y[row] = s;
        }
    }
}

__global__ void __launch_bounds__(THREADS, 8)
batched_teacher_policy_kernel(const float* __restrict__ obs,
                              const float* __restrict__ mean,
                              const float* __restrict__ stdv,
                              const float* __restrict__ W0,
                              const float* __restrict__ b0,
                              const float* __restrict__ W1,
                              const float* __restrict__ b1,
                              const float* __restrict__ W2,
                              const float* __restrict__ b2,
                              const float* __restrict__ W3,
                              const float* __restrict__ b3,
                              float* __restrict__ out) {
    const int tid = threadIdx.x;

    __shared__ __align__(16) float bufA[512];
    __shared__ __align__(16) float bufB[512];

    #pragma unroll
    for (int s = 0; s < SAMPLES_PER_CTA; s++) {
        const int n = blockIdx.x * SAMPLES_PER_CTA + s;

        // x0 = clip((obs-mean)/std, -5, 5)
        if (tid < OBS) {
            const int i = n * OBS + tid;
            float v = (obs[i] - mean[i]) / stdv[i];
            bufA[tid] = fminf(fmaxf(v, -5.0f), 5.0f);
        }
        __syncthreads();

        // L0: 512 x 48, 16 lanes per row (12 float4/row)
        layer2<512, 48, 16, true>(W0 + (size_t)n * 512 * 48,
                                  b0 + (size_t)n * 512, bufA, bufB);
        __syncthreads();

        // L1: 256 x 512
        layer2<256, 512, 32, true>(W1 + (size_t)n * 256 * 512,
                                   b1 + (size_t)n * 256, bufB, bufA);
        __syncthreads();

        // L2: 128 x 256
        layer2<128, 256, 32, true>(W2 + (size_t)n * 128 * 256,
                                   b2 + (size_t)n * 128, bufA, bufB);
        __syncthreads();

        // L3: 12 x 128, no ELU
        layer1<12, 128, 32, false>(W3 + (size_t)n * 12 * 128,
                                   b3 + (size_t)n * 12, bufB, bufA);
        __syncthreads();

        if (tid < 12)
            out[n * 12 + tid] = tanhf(bufA[tid]);
        __syncthreads();
    }
}

extern "C" void kernel_launch(void* const* d_in, const int* in_sizes, int n_in,
                              void* d_out, int out_size) {
    const float* obs  = (const float*)d_in[0];
    const float* mean = (const float*)d_in[1];
    const float* stdv = (const float*)d_in[2];
    const float* W0   = (const float*)d_in[3];
    const float* b0   = (const float*)d_in[4];
    const float* W1   = (const float*)d_in[5];
    const float* b1   = (const float*)d_in[6];
    const float* W2   = (const float*)d_in[7];
    const float* b2   = (const float*)d_in[8];
    const float* W3   = (const float*)d_in[9];
    const float* b3   = (const float*)d_in[10];
    float* out = (float*)d_out;

    batched_teacher_policy_kernel<<<NSAMP / SAMPLES_PER_CTA, THREADS>>>(
        obs, mean, stdv, W0, b0, W1, b1, W2, b2, W3, b3, out);
}

// round 4
// speedup vs baseline: 1.0316x; 1.0316x over previous
#include <cuda_runtime.h>
#include <math.h>

// Problem shape (fixed by the reference)
#define NSAMP 2048
#define OBS   48
// Layers: (out, in)
// L0: 512 x 48   L1: 256 x 512   L2: 128 x 256   L3: 12 x 128

// 128 threads/CTA, one sample per CTA, grid = 2048.
// Capacity: 152 SMs x 16 CTAs (2048-thread cap) = 2432 >= 2048 -> single
// fully-resident wave, no wave-transition or second-wave underfill.
#define THREADS 128

__device__ __forceinline__ float elu(float s) {
    return (s > 0.0f) ? s : (__expf(s) - 1.0f);
}

// Two rows per group per iteration: 8 independent weight loads in flight
// before any dependent FMA/reduce. Biases prefetched before the dot loop.
// Requires OUT % (2 * THREADS/G) == 0.
template <int OUT, int IN, int G, bool ACT>
__device__ __forceinline__ void layer2(const float* __restrict__ W,
                                       const float* __restrict__ b,
                                       const float* __restrict__ x,
                                       float* __restrict__ y) {
    constexpr int NV = IN / 4;          // float4 per row
    constexpr int NG = THREADS / G;     // groups per block
    const int gid = threadIdx.x / G;
    const int gl  = threadIdx.x % G;
    const float4* __restrict__ xv = reinterpret_cast<const float4*>(x);

    #pragma unroll
    for (int row = gid; row < OUT; row += 2 * NG) {
        const int row1 = row + NG;
        float bias0 = __ldcs(b + row);
        float bias1 = __ldcs(b + row1);
        const float4* __restrict__ Wr0 =
            reinterpret_cast<const float4*>(W + (size_t)row  * IN);
        const float4* __restrict__ Wr1 =
            reinterpret_cast<const float4*>(W + (size_t)row1 * IN);
        float s0 = 0.0f, s1 = 0.0f;
        #pragma unroll
        for (int j = gl; j < NV; j += G) {
            float4 w0 = __ldcs(Wr0 + j);
            float4 w1 = __ldcs(Wr1 + j);
            float4 v  = xv[j];
            s0 = fmaf(w0.x, v.x, s0);
            s0 = fmaf(w0.y, v.y, s0);
            s0 = fmaf(w0.z, v.z, s0);
            s0 = fmaf(w0.w, v.w, s0);
            s1 = fmaf(w1.x, v.x, s1);
            s1 = fmaf(w1.y, v.y, s1);
            s1 = fmaf(w1.z, v.z, s1);
            s1 = fmaf(w1.w, v.w, s1);
        }
        #pragma unroll
        for (int o = G / 2; o >= 1; o >>= 1) {
            s0 += __shfl_xor_sync(0xffffffffu, s0, o);
            s1 += __shfl_xor_sync(0xffffffffu, s1, o);
        }
        if (gl == 0) {
            s0 += bias0;
            s1 += bias1;
            if (ACT) { s0 = elu(s0); s1 = elu(s1); }
            y[row]  = s0;
            y[row1] = s1;
        }
    }
}

// Single-row variant for the tiny final layer.
template <int OUT, int IN, int G, bool ACT>
__device__ __forceinline__ void layer1(const float* __restrict__ W,
                                       const float* __restrict__ b,
                                       const float* __restrict__ x,
                                       float* __restrict__ y) {
    constexpr int NV = IN / 4;
    constexpr int NG = THREADS / G;
    const int gid = threadIdx.x / G;
    const int gl  = threadIdx.x % G;
    const float4* __restrict__ xv = reinterpret_cast<const float4*>(x);

    for (int row = gid; row < OUT; row += NG) {
        float bias = __ldcs(b + row);
        const float4* __restrict__ Wr =
            reinterpret_cast<const float4*>(W + (size_t)row * IN);
        float s = 0.0f;
        #pragma unroll
        for (int j = gl; j < NV; j += G) {
            float4 w = __ldcs(Wr + j);
            float4 v = xv[j];
            s = fmaf(w.x, v.x, s);
            s = fmaf(w.y, v.y, s);
            s = fmaf(w.z, v.z, s);
            s = fmaf(w.w, v.w, s);
        }
        #pragma unroll
        for (int o = G / 2; o >= 1; o >>= 1)
            s += __shfl_xor_sync(0xffffffffu, s, o);
        if (gl == 0) {
            s += bias;
            if (ACT) s = elu(s);
            y[row] = s;
        }
    }
}

__global__ void __launch_bounds__(THREADS, 16)
batched_teacher_policy_kernel(const float* __restrict__ obs,
                              const float* __restrict__ mean,
                              const float* __restrict__ stdv,
                              const float* __restrict__ W0,
                              const float* __restrict__ b0,
                              const float* __restrict__ W1,
                              const float* __restrict__ b1,
                              const float* __restrict__ W2,
                              const float* __restrict__ b2,
                              const float* __restrict__ W3,
                              const float* __restrict__ b3,
                              float* __restrict__ out) {
    const int n = blockIdx.x;
    const int tid = threadIdx.x;

    __shared__ __align__(16) float bufA[512];
    __shared__ __align__(16) float bufB[512];

    // x0 = clip((obs-mean)/std, -5, 5)
    if (tid < OBS) {
        const int i = n * OBS + tid;
        float v = (obs[i] - mean[i]) / stdv[i];
        bufA[tid] = fminf(fmaxf(v, -5.0f), 5.0f);
    }
    __syncthreads();

    // L0: 512 x 48, 16 lanes per row (12 float4/row)
    layer2<512, 48, 16, true>(W0 + (size_t)n * 512 * 48,
                              b0 + (size_t)n * 512, bufA, bufB);
    __syncthreads();

    // L1: 256 x 512
    layer2<256, 512, 32, true>(W1 + (size_t)n * 256 * 512,
                               b1 + (size_t)n * 256, bufB, bufA);
    __syncthreads();

    // L2: 128 x 256
    layer2<128, 256, 32, true>(W2 + (size_t)n * 128 * 256,
                               b2 + (size_t)n * 128, bufA, bufB);
    __syncthreads();

    // L3: 12 x 128, no ELU
    layer1<12, 128, 32, false>(W3 + (size_t)n * 12 * 128,
                               b3 + (size_t)n * 12, bufB, bufA);
    __syncthreads();

    if (tid < 12)
        out[n * 12 + tid] = tanhf(bufA[tid]);
}

extern "C" void kernel_launch(void* const* d_in, const int* in_sizes, int n_in,
                              void* d_out, int out_size) {
    const float* obs  = (const float*)d_in[0];
    const float* mean = (const float*)d_in[1];
    const float* stdv = (const float*)d_in[2];
    const float* W0   = (const float*)d_in[3];
    const float* b0   = (const float*)d_in[4];
    const float* W1   = (const float*)d_in[5];
    const float* b1   = (const float*)d_in[6];
    const float* W2   = (const float*)d_in[7];
    const float* b2   = (const float*)d_in[8];
    const float* W3   = (const float*)d_in[9];
    const float* b3   = (const float*)d_in[10];
    float* out = (float*)d_out;

    batched_teacher_policy_kernel<<<NSAMP, THREADS>>>(
        obs, mean, stdv, W0, b0, W1, b1, W2, b2, W3, b3, out);
}

// round 5
// speedup vs baseline: 1.0512x; 1.0190x over previous
#include <cuda_runtime.h>
#include <math.h>

// Problem shape (fixed by the reference)
#define NSAMP 2048
#define OBS   48
// Layers: (out, in)
// L0: 512 x 48   L1: 256 x 512   L2: 128 x 256   L3: 12 x 128

// Inter-layer activation scratch (device globals: allocation-free).
__device__ __align__(16) float g_a0[NSAMP * 512];
__device__ __align__(16) float g_a1[NSAMP * 256];
__device__ __align__(16) float g_a2[NSAMP * 128];

__device__ __forceinline__ float elu(float s) {
    return (s > 0.0f) ? s : (__expf(s) - 1.0f);
}

// ---------------------------------------------------------------------------
// L0: obs-normalization fused with 512x48 layer. 256 threads, 16-lane groups
// (48 floats = 12 float4 per row), 64 rows per CTA -> 8 CTAs per sample.
// ---------------------------------------------------------------------------
__global__ void __launch_bounds__(256, 8)
k_l0(const float* __restrict__ obs, const float* __restrict__ mean,
     const float* __restrict__ stdv, const float* __restrict__ W0,
     const float* __restrict__ b0) {
    const int b  = blockIdx.x;
    const int n  = b >> 3;             // sample
    const int rb = (b & 7) * 64;       // row base within sample
    const int tid = threadIdx.x;

    __shared__ __align__(16) float xs[OBS];
    if (tid < OBS) {
        const int i = n * OBS + tid;
        float v = (obs[i] - mean[i]) / stdv[i];
        xs[tid] = fminf(fmaxf(v, -5.0f), 5.0f);
    }
    __syncthreads();

    const int gid = tid >> 4;          // 16 groups
    const int gl  = tid & 15;
    const float4* __restrict__ xv = reinterpret_cast<const float4*>(xs);
    const float* __restrict__ W = W0 + (size_t)n * 512 * 48;
    const float* __restrict__ bb = b0 + (size_t)n * 512;
    float* __restrict__ y = g_a0 + (size_t)n * 512;

    #pragma unroll
    for (int r0 = rb + gid; r0 < rb + 64; r0 += 32) {
        const int r1 = r0 + 16;
        float bias0 = __ldcs(bb + r0);
        float bias1 = __ldcs(bb + r1);
        const float4* __restrict__ Wr0 =
            reinterpret_cast<const float4*>(W + (size_t)r0 * 48);
        const float4* __restrict__ Wr1 =
            reinterpret_cast<const float4*>(W + (size_t)r1 * 48);
        float s0 = 0.0f, s1 = 0.0f;
        if (gl < 12) {                 // 12 float4 per row, 16 lanes
            float4 w0 = __ldcs(Wr0 + gl);
            float4 w1 = __ldcs(Wr1 + gl);
            float4 v  = xv[gl];
            s0 = fmaf(w0.x, v.x, fmaf(w0.y, v.y, fmaf(w0.z, v.z, w0.w * v.w)));
            s1 = fmaf(w1.x, v.x, fmaf(w1.y, v.y, fmaf(w1.z, v.z, w1.w * v.w)));
        }
        #pragma unroll
        for (int o = 8; o >= 1; o >>= 1) {
            s0 += __shfl_xor_sync(0xffffffffu, s0, o);
            s1 += __shfl_xor_sync(0xffffffffu, s1, o);
        }
        if (gl == 0) {
            y[r0] = elu(s0 + bias0);
            y[r1] = elu(s1 + bias1);
        }
    }
}

// ---------------------------------------------------------------------------
// Generic hidden layer: OUT x IN, warp per row-pair, ROWS_PER_CTA rows/CTA.
// 256 threads = 8 warps -> 16 rows per pass.
// ---------------------------------------------------------------------------
template <int OUT, int IN, int ROWS_PER_CTA, bool ACT>
__global__ void __launch_bounds__(256, 8)
k_layer(const float* __restrict__ Wg, const float* __restrict__ bg,
        const float* __restrict__ xg, float* __restrict__ yg) {
    constexpr int CTAS_PER_SAMPLE = OUT / ROWS_PER_CTA;
    constexpr int NV = IN / 4;
    const int b  = blockIdx.x;
    const int n  = b / CTAS_PER_SAMPLE;
    const int rb = (b % CTAS_PER_SAMPLE) * ROWS_PER_CTA;
    const int tid = threadIdx.x;
    const int wid = tid >> 5;          // 8 warps
    const int gl  = tid & 31;

    __shared__ __align__(16) float xs[IN];
    {
        const float4* __restrict__ src =
            reinterpret_cast<const float4*>(xg + (size_t)n * IN);
        float4* dst = reinterpret_cast<float4*>(xs);
        if (tid < NV) dst[tid] = src[tid];   // NV <= 128 <= 256
    }
    __syncthreads();

    const float4* __restrict__ xv = reinterpret_cast<const float4*>(xs);
    const float* __restrict__ W = Wg + (size_t)n * OUT * IN;
    const float* __restrict__ bb = bg + (size_t)n * OUT;
    float* __restrict__ y = yg + (size_t)n * OUT;

    #pragma unroll
    for (int r0 = rb + wid; r0 < rb + ROWS_PER_CTA; r0 += 16) {
        const int r1 = r0 + 8;
        float bias0 = __ldcs(bb + r0);
        float bias1 = __ldcs(bb + r1);
        const float4* __restrict__ Wr0 =
            reinterpret_cast<const float4*>(W + (size_t)r0 * IN);
        const float4* __restrict__ Wr1 =
            reinterpret_cast<const float4*>(W + (size_t)r1 * IN);
        float s0 = 0.0f, s1 = 0.0f;
        #pragma unroll
        for (int j = gl; j < NV; j += 32) {
            float4 w0 = __ldcs(Wr0 + j);
            float4 w1 = __ldcs(Wr1 + j);
            float4 v  = xv[j];
            s0 = fmaf(w0.x, v.x, s0);
            s0 = fmaf(w0.y, v.y, s0);
            s0 = fmaf(w0.z, v.z, s0);
            s0 = fmaf(w0.w, v.w, s0);
            s1 = fmaf(w1.x, v.x, s1);
            s1 = fmaf(w1.y, v.y, s1);
            s1 = fmaf(w1.z, v.z, s1);
            s1 = fmaf(w1.w, v.w, s1);
        }
        #pragma unroll
        for (int o = 16; o >= 1; o >>= 1) {
            s0 += __shfl_xor_sync(0xffffffffu, s0, o);
            s1 += __shfl_xor_sync(0xffffffffu, s1, o);
        }
        if (gl == 0) {
            s0 += bias0;
            s1 += bias1;
            if (ACT) { s0 = elu(s0); s1 = elu(s1); }
            y[r0] = s0;
            y[r1] = s1;
        }
    }
}

// ---------------------------------------------------------------------------
// L3: 12 x 128 + tanh. One CTA (128 threads = 4 warps) per sample.
// ---------------------------------------------------------------------------
__global__ void __launch_bounds__(128, 16)
k_l3(const float* __restrict__ W3, const float* __restrict__ b3,
     float* __restrict__ out) {
    const int n = blockIdx.x;
    const int tid = threadIdx.x;
    const int wid = tid >> 5;
    const int gl  = tid & 31;

    __shared__ __align__(16) float xs[128];
    {
        const float4* __restrict__ src =
            reinterpret_cast<const float4*>(g_a2 + (size_t)n * 128);
        if (tid < 32) reinterpret_cast<float4*>(xs)[tid] = src[tid];
    }
    __syncthreads();

    const float4* __restrict__ xv = reinterpret_cast<const float4*>(xs);
    const float* __restrict__ W = W3 + (size_t)n * 12 * 128;
    const float* __restrict__ bb = b3 + (size_t)n * 12;

    #pragma unroll
    for (int row = wid; row < 12; row += 4) {
        float bias = __ldcs(bb + row);
        const float4* __restrict__ Wr =
            reinterpret_cast<const float4*>(W + (size_t)row * 128);
        float4 w = __ldcs(Wr + gl);
        float4 v = xv[gl];
        float s = fmaf(w.x, v.x, fmaf(w.y, v.y, fmaf(w.z, v.z, w.w * v.w)));
        #pragma unroll
        for (int o = 16; o >= 1; o >>= 1)
            s += __shfl_xor_sync(0xffffffffu, s, o);
        if (gl == 0)
            out[n * 12 + row] = tanhf(s + bias);
    }
}

extern "C" void kernel_launch(void* const* d_in, const int* in_sizes, int n_in,
                              void* d_out, int out_size) {
    const float* obs  = (const float*)d_in[0];
    const float* mean = (const float*)d_in[1];
    const float* stdv = (const float*)d_in[2];
    const float* W0   = (const float*)d_in[3];
    const float* b0   = (const float*)d_in[4];
    const float* W1   = (const float*)d_in[5];
    const float* b1   = (const float*)d_in[6];
    const float* W2   = (const float*)d_in[7];
    const float* b2   = (const float*)d_in[8];
    const float* W3   = (const float*)d_in[9];
    const float* b3   = (const float*)d_in[10];
    float* out = (float*)d_out;

    float* a0;  cudaGetSymbolAddress((void**)&a0, g_a0);
    float* a1;  cudaGetSymbolAddress((void**)&a1, g_a1);
    float* a2;  cudaGetSymbolAddress((void**)&a2, g_a2);

    // L0: 8 CTAs/sample x 2048
    k_l0<<<NSAMP * 8, 256>>>(obs, mean, stdv, W0, b0);
    // L1: 256x512, 32 rows/CTA -> 8 CTAs/sample
    k_layer<256, 512, 32, true><<<NSAMP * 8, 256>>>(W1, b1, a0, a1);
    // L2: 128x256, 16 rows/CTA -> 8 CTAs/sample
    k_layer<128, 256, 16, true><<<NSAMP * 8, 256>>>(W2, b2, a1, a2);
    // L3: 12x128 + tanh, 1 CTA/sample
    k_l3<<<NSAMP, 128>>>(W3, b3, out);
}